// round 14
// baseline (speedup 1.0000x reference)
#include <cuda_runtime.h>
#include <stdint.h>

// UniformShardedEmbeddingBags: weights [E,T,D] fp32, indices [B,T,L] int32 -> out [B,T,D] fp32
// E=200000, T=16, D=64, B=4096, L=20
#define EB_E 200000
#define EB_T 16
#define EB_D 64
#define EB_L 20
#define EB_B 4096

// CONVERGED KERNEL (R7 structure; R12 rerun showed +-1.5us run noise, so
// R7/R8/R9/R12 are statistically tied at ~50us with DRAM bytes at the dedup
// floor ~296MB and DRAM-active at the ~74-76% random-256B pattern ceiling).
//
//  - one warp per bag; each lane owns one float2 (8B) slot of the 256B row
//    (32 lanes x 8B = two coalesced 128B lines per gathered row, one LDG.64)
//  - PHASE-SPLIT burst: all 20 row loads issued into v[20] before any
//    accumulation (burst-issue beat consume/issue pipelining, cp.async,
//    2-bag ILP, and streaming stores in R5-R11 ablations)
//  - TABLE-MAJOR grid: concurrent working set ~2 tables (~34MB) << 126MB L2,
//    so the ~1.22x per-table row reuse is L2-captured.
//  - NEW: block-wide index staging through shared memory - one coalesced
//    640B load for all 160 indices of the block, then conflict-free broadcast
//    LDS in the burst loop. Removes the per-warp idx-LDG -> 20xSHFL chain
//    from the prologue and 20 MIO shfl ops per bag from the issue stream.
__global__ __launch_bounds__(256) void embbag_kernel(
    const float* __restrict__ weights,
    const int* __restrict__ indices,
    float* __restrict__ out)
{
    __shared__ int sidx[8 * EB_L];   // 160 indices = this block's 8 bags

    const int warp = threadIdx.x >> 5;                  // 0..7
    const int lane = threadIdx.x & 31;

    const int t = blockIdx.x >> 9;                      // table 0..15 (512 blocks each)
    const int bbase = (blockIdx.x & 511) << 3;          // first batch of this block
    const int b = bbase + warp;
    const int bag = b * EB_T + t;

    // Stage all 160 indices with one coalesced block-wide transaction.
    // Bags of this block are (bbase+w)*16 + t -> their index rows are
    // NOT contiguous (stride 16*20 ints), so load per-bag rows coalesced:
    // thread i = w*32+j: warp w's lanes 0..19 load bag w's 20 indices.
    if (lane < EB_L)
        sidx[warp * EB_L + lane] = __ldg(indices + (size_t)bag * EB_L + lane);
    __syncthreads();

    const float2* wbase = reinterpret_cast<const float2*>(weights) + lane;
    const int* myidx = &sidx[warp * EB_L];

    // Phase 1: issue ALL row loads (no consumer in between).
    float2 v[EB_L];
#pragma unroll
    for (int l = 0; l < EB_L; ++l) {
        int e = myidx[l];   // LDS broadcast, conflict-free
        v[l] = __ldg(wbase + ((size_t)e * EB_T + t) * (EB_D / 2));
    }

    // Phase 2: reduce.
    float accx = 0.f, accy = 0.f;
#pragma unroll
    for (int l = 0; l < EB_L; ++l) {
        accx += v[l].x;
        accy += v[l].y;
    }

    reinterpret_cast<float2*>(out)[(size_t)bag * 32 + lane] = make_float2(accx, accy);
}

extern "C" void kernel_launch(void* const* d_in, const int* in_sizes, int n_in,
                              void* d_out, int out_size)
{
    // weights = 204,800,000 elems ; indices = 1,310,720 elems
    const float* weights = (const float*)d_in[0];
    const int*   indices = (const int*)d_in[1];
    if (n_in >= 2 && in_sizes[0] < in_sizes[1]) {
        weights = (const float*)d_in[1];
        indices = (const int*)d_in[0];
    }
    float* out = (float*)d_out;

    const int block = 256;                 // 8 warps = 8 bags per block
    const int grid = EB_T * 512;           // 8192 blocks, table-major
    embbag_kernel<<<grid, block>>>(weights, indices, out);
}